// round 4
// baseline (speedup 1.0000x reference)
#include <cuda_runtime.h>

// Problem constants
#define B   16
#define C   16
#define H   256
#define W   256
#define F   32
#define TY  32      // output tile rows per block
#define TX  64      // output tile cols per block
#define FG  8       // filters per block
#define IPITCH 68   // shared input row pitch (floats, 16B-aligned rows)
#define IROWS 34
#define ICOLS 66    // valid cols stored (cols 66,67 of pitch unused garbage)
#define NLD 9       // ceil(34*66/256)

typedef unsigned long long ull;

// packed f32x2 FMA (SASS FFMA2)
__device__ __forceinline__ void fma2(ull& d, ull a, ull b) {
    asm("fma.rn.f32x2 %0, %1, %2, %0;" : "+l"(d) : "l"(a), "l"(b));
}
__device__ __forceinline__ ull pack2(float lo, float hi) {
    ull p;
    asm("mov.b64 %0, {%1, %2};" : "=l"(p) : "f"(lo), "f"(hi));
    return p;
}
__device__ __forceinline__ void unpack2(ull p, float& lo, float& hi) {
    asm("mov.b64 {%0, %1}, %2;" : "=f"(lo), "=f"(hi) : "l"(p));
}

__global__ __launch_bounds__(256)
void conv3x3_sig_kernel(const float* __restrict__ x,
                        const float* __restrict__ weights,
                        const float* __restrict__ biases,
                        float* __restrict__ out) {
    // grid: (W/TX, H/TY, B * (F/FG)) = (4, 8, 64)
    const int tx = blockIdx.x;
    const int ty = blockIdx.y;
    const int b  = blockIdx.z >> 2;
    const int g  = blockIdx.z & 3;

    const int tid = threadIdx.x;        // 0..255
    const int row = tid >> 3;           // 0..31 output row within tile
    const int cg8 = (tid & 7) * 8;      // output col offset (8 px/thread)

    __shared__ __align__(16) float s_in[2][IROWS * IPITCH];
    __shared__ __align__(16) float4 s_w4[C * 9 * (FG / 2)]; // (w0,w0,w1,w1) per 2 filters

    // ---- stage weights: layout [(c*9 + tap)*32 + f] ----
    for (int i = tid; i < C * 9 * (FG / 2); i += 256) {
        const int c   = i / 36;
        const int rem = i - c * 36;
        const int tap = rem >> 2;
        const int fp  = rem & 3;
        const float w0 = weights[(c * 9 + tap) * F + g * FG + 2 * fp + 0];
        const float w1 = weights[(c * 9 + tap) * F + g * FG + 2 * fp + 1];
        s_w4[i] = make_float4(w0, w0, w1, w1);
    }

    const int y0 = ty * TY - 1;         // input tile origin (with pad)
    const int x0 = tx * TX - 1;

    // ---- precompute tile-load geometry (channel-invariant) ----
    int  goff[NLD];
    int  sdst[NLD];
    bool ldp[NLD];
    #pragma unroll
    for (int i = 0; i < NLD; i++) {
        const int idx = tid + 256 * i;
        const bool slot = (idx < IROWS * ICOLS);
        const int r  = idx / ICOLS;
        const int cc = idx - r * ICOLS;
        const int gy = y0 + r;
        const int gxx = x0 + cc;
        ldp[i]  = slot && ((unsigned)gy < (unsigned)H) && ((unsigned)gxx < (unsigned)W);
        goff[i] = gy * W + gxx;
        sdst[i] = slot ? (r * IPITCH + cc) : -1;
    }

    const float* gx0 = x + ((size_t)b * C) * H * W;

    // accumulators: 8 filters x 4 f32x2 pairs (pixels {0,1}{2,3}{4,5}{6,7})
    ull acc[FG * 4];
    #pragma unroll
    for (int i = 0; i < FG * 4; i++) acc[i] = 0ull;

    // ---- prologue: channel 0 -> buffer 0 ----
    {
        float v[NLD];
        #pragma unroll
        for (int i = 0; i < NLD; i++) v[i] = ldp[i] ? gx0[goff[i]] : 0.f;
        #pragma unroll
        for (int i = 0; i < NLD; i++) if (sdst[i] >= 0) s_in[0][sdst[i]] = v[i];
    }
    __syncthreads();

    for (int c = 0; c < C; c++) {
        const int cur = c & 1;

        // ---- issue next channel's loads (latency overlapped with compute) ----
        float nv[NLD];
        if (c + 1 < C) {
            const float* gn = gx0 + (size_t)(c + 1) * H * W;
            #pragma unroll
            for (int i = 0; i < NLD; i++) nv[i] = ldp[i] ? gn[goff[i]] : 0.f;
        }

        // ---- compute channel c ----
        const ulonglong2* wrow =
            reinterpret_cast<const ulonglong2*>(&s_w4[c * 36]);

        #pragma unroll
        for (int kh = 0; kh < 3; kh++) {
            const float* base = &s_in[cur][(row + kh) * IPITCH + cg8];
            const float4 a  = *reinterpret_cast<const float4*>(base);      // v0..v3
            const float4 bq = *reinterpret_cast<const float4*>(base + 4);  // v4..v7
            const float4 cq = *reinterpret_cast<const float4*>(base + 8);  // v8..v11

            // even pairs: free register-pair aliasing
            const ull e0 = pack2(a.x, a.y);
            const ull e1 = pack2(a.z, a.w);
            const ull e2 = pack2(bq.x, bq.y);
            const ull e3 = pack2(bq.z, bq.w);
            const ull e4 = pack2(cq.x, cq.y);
            // odd pairs: real packs
            const ull o0 = pack2(a.y, a.z);
            const ull o1 = pack2(a.w, bq.x);
            const ull o2 = pack2(bq.y, bq.z);
            const ull o3 = pack2(bq.w, cq.x);

            const ull P[3][4] = {
                { e0, e1, e2, e3 },   // kw=0
                { o0, o1, o2, o3 },   // kw=1
                { e1, e2, e3, e4 }    // kw=2
            };

            #pragma unroll
            for (int kw = 0; kw < 3; kw++) {
                #pragma unroll
                for (int fp = 0; fp < 4; fp++) {
                    const ulonglong2 wv = wrow[(kh * 3 + kw) * 4 + fp]; // LDS.128 bcast
                    #pragma unroll
                    for (int q = 0; q < 4; q++) {
                        fma2(acc[(fp * 2 + 0) * 4 + q], P[kw][q], wv.x);
                        fma2(acc[(fp * 2 + 1) * 4 + q], P[kw][q], wv.y);
                    }
                }
            }
        }

        // ---- store next channel into other buffer ----
        if (c + 1 < C) {
            #pragma unroll
            for (int i = 0; i < NLD; i++)
                if (sdst[i] >= 0) s_in[1 - cur][sdst[i]] = nv[i];
        }
        __syncthreads();
    }

    // ---- epilogue: bias + sigmoid + store ----
    const int oy = ty * TY + row;
    const int ox = tx * TX + cg8;
    #pragma unroll
    for (int f = 0; f < FG; f++) {
        const int fo = g * FG + f;
        float r[8];
        #pragma unroll
        for (int q = 0; q < 4; q++)
            unpack2(acc[f * 4 + q], r[2 * q], r[2 * q + 1]);

        const float4 b0 = *reinterpret_cast<const float4*>(
            &biases[((size_t)fo * H + oy) * W + ox]);
        const float4 b1 = *reinterpret_cast<const float4*>(
            &biases[((size_t)fo * H + oy) * W + ox + 4]);
        r[0] += b0.x; r[1] += b0.y; r[2] += b0.z; r[3] += b0.w;
        r[4] += b1.x; r[5] += b1.y; r[6] += b1.z; r[7] += b1.w;

        float4 o0, o1;
        o0.x = 1.f / (1.f + __expf(-r[0]));
        o0.y = 1.f / (1.f + __expf(-r[1]));
        o0.z = 1.f / (1.f + __expf(-r[2]));
        o0.w = 1.f / (1.f + __expf(-r[3]));
        o1.x = 1.f / (1.f + __expf(-r[4]));
        o1.y = 1.f / (1.f + __expf(-r[5]));
        o1.z = 1.f / (1.f + __expf(-r[6]));
        o1.w = 1.f / (1.f + __expf(-r[7]));

        float* op = &out[(((size_t)b * F + fo) * H + oy) * W + ox];
        *reinterpret_cast<float4*>(op)     = o0;
        *reinterpret_cast<float4*>(op + 4) = o1;
    }
}

extern "C" void kernel_launch(void* const* d_in, const int* in_sizes, int n_in,
                              void* d_out, int out_size) {
    const float* x       = (const float*)d_in[0];
    const float* weights = (const float*)d_in[1];
    const float* biases  = (const float*)d_in[2];
    float* out = (float*)d_out;

    dim3 grid(W / TX, H / TY, B * (F / FG));   // (4, 8, 64)
    dim3 block(256);
    conv3x3_sig_kernel<<<grid, block>>>(x, weights, biases, out);
}